// round 8
// baseline (speedup 1.0000x reference)
#include <cuda_runtime.h>

// ---------------- problem constants ----------------
#define N1v 8192
#define N2v 4096
#define Tv 15
#define Bv 4
#define E1v 131072
#define E2v 65536
#define Kv 12
#define G1v 64
#define G2v 32
#define Cv 6

#define D1v 60                    // T*B comps per node, layer1 (layout t*4+b)
#define T1_SLOT (N1v * D1v)       // 491520
#define T2_SLOT (N2v * 64 * Bv)   // 1048576, layout [b][n][g]
#define T2_BOFF (N2v * 64)        // 262144

// ---------------- scratch (device globals; allocation-free) ----------------
__device__ int   d_is64;          // 1 if edge_index buffers are int64, 0 if int32
__device__ float d_deg1[N1v];
__device__ float d_dinv1[N1v];
__device__ float d_deg2[N2v];
__device__ float d_dinv2[N2v];
__device__ int   d_cnt1[N1v];
__device__ int   d_fill1[N1v];
__device__ int   d_row1[N1v + 1];
__device__ int   d_cnt2[N2v];
__device__ int   d_fill2[N2v];
__device__ int   d_row2[N2v + 1];
__device__ int   d_csrc1[E1v];
__device__ float d_cval1[E1v];
__device__ int   d_csrc2[E2v];
__device__ float d_cval2[E2v];
__device__ float d_T1[Kv * T1_SLOT];    // 23.6 MB : Cheb tensors layer1, [k][n*60 + t*4 + b]
__device__ float d_y1[N1v * 256];       // 8 MB    : relu(conv1), [n*256 + g*4 + b]
__device__ float d_T2g[Kv * T2_SLOT];   // 50.3 MB : Cheb tensors layer2, [k][b][n][g]
__device__ float d_y2[N2v * 128];       // 2 MB    : conv2 out, [n*128 + g*4 + b] (== torch flat order)
__device__ float d_logits[Bv * Cv];

// ---------------- dtype detection for edge indices ----------------
// int64 indices in [0, 8192): every odd 32-bit word is 0. Random int32
// indices: probability all 32 odd words are 0 is ~(1/8192)^32 == 0.
__global__ void detect_kernel(const int* __restrict__ ei1_as_i32) {
    if (threadIdx.x == 0) {
        int is64 = 1;
        for (int i = 1; i < 64; i += 2)
            if (ei1_as_i32[i] != 0) { is64 = 0; break; }
        d_is64 = is64;
    }
}

__device__ __forceinline__ int load_idx(const void* ei, int pos, int is64) {
    if (is64) return (int)((const long long*)ei)[pos];
    return ((const int*)ei)[pos];
}

// ---------------- init / graph normalization ----------------
__global__ void zero_kernel() {
    int i = blockIdx.x * 256 + threadIdx.x;
    if (i < T2_SLOT) d_T2g[i] = 0.0f;          // GEMM accum target (T2 slot 0)
    if (i < N1v) { d_deg1[i] = 0.0f; d_cnt1[i] = 0; d_fill1[i] = 0; }
    if (i < N2v) { d_deg2[i] = 0.0f; d_cnt2[i] = 0; d_fill2[i] = 0; }
}

__global__ void deg1_kernel(const void* __restrict__ ei, const float* __restrict__ w) {
    int e = blockIdx.x * 256 + threadIdx.x;
    if (e < E1v) {
        int is64 = d_is64;
        int d = load_idx(ei, E1v + e, is64);
        if ((unsigned)d < N1v) {
            atomicAdd(&d_deg1[d], w[e]);
            atomicAdd(&d_cnt1[d], 1);
        }
    }
}
__global__ void deg2_kernel(const void* __restrict__ ei, const float* __restrict__ w) {
    int e = blockIdx.x * 256 + threadIdx.x;
    if (e < E2v) {
        int is64 = d_is64;
        int d = load_idx(ei, E2v + e, is64);
        if ((unsigned)d < N2v) {
            atomicAdd(&d_deg2[d], w[e]);
            atomicAdd(&d_cnt2[d], 1);
        }
    }
}

__global__ void dinv_kernel() {
    int i = blockIdx.x * 256 + threadIdx.x;
    if (i < N1v) { float v = d_deg1[i]; d_dinv1[i] = (v > 0.0f) ? rsqrtf(v) : 0.0f; }
    if (i < N2v) { float v = d_deg2[i]; d_dinv2[i] = (v > 0.0f) ? rsqrtf(v) : 0.0f; }
}

// single-block exclusive scans of cnt -> row  (8192 then 4096 entries)
__global__ void scan_kernel() {
    __shared__ int sh[1024];
    int tid = threadIdx.x;
    {
        int v[8]; int s = 0;
#pragma unroll
        for (int j = 0; j < 8; j++) { v[j] = d_cnt1[tid * 8 + j]; s += v[j]; }
        sh[tid] = s; __syncthreads();
        for (int off = 1; off < 1024; off <<= 1) {
            int x = (tid >= off) ? sh[tid - off] : 0;
            __syncthreads();
            sh[tid] += x;
            __syncthreads();
        }
        int run = sh[tid] - s;
#pragma unroll
        for (int j = 0; j < 8; j++) { d_row1[tid * 8 + j] = run; run += v[j]; }
        if (tid == 1023) d_row1[N1v] = run;
    }
    __syncthreads();
    {
        int v[4]; int s = 0;
#pragma unroll
        for (int j = 0; j < 4; j++) { v[j] = d_cnt2[tid * 4 + j]; s += v[j]; }
        sh[tid] = s; __syncthreads();
        for (int off = 1; off < 1024; off <<= 1) {
            int x = (tid >= off) ? sh[tid - off] : 0;
            __syncthreads();
            sh[tid] += x;
            __syncthreads();
        }
        int run = sh[tid] - s;
#pragma unroll
        for (int j = 0; j < 4; j++) { d_row2[tid * 4 + j] = run; run += v[j]; }
        if (tid == 1023) d_row2[N2v] = run;
    }
}

__global__ void fill1_kernel(const void* __restrict__ ei, const float* __restrict__ w) {
    int e = blockIdx.x * 256 + threadIdx.x;
    if (e < E1v) {
        int is64 = d_is64;
        int s = load_idx(ei, e, is64);
        int d = load_idx(ei, E1v + e, is64);
        if ((unsigned)s < N1v && (unsigned)d < N1v) {
            float v = -w[e] * d_dinv1[s] * d_dinv1[d];
            int p = d_row1[d] + atomicAdd(&d_fill1[d], 1);
            if ((unsigned)p < E1v) { d_csrc1[p] = s; d_cval1[p] = v; }
        }
    }
}
__global__ void fill2_kernel(const void* __restrict__ ei, const float* __restrict__ w) {
    int e = blockIdx.x * 256 + threadIdx.x;
    if (e < E2v) {
        int is64 = d_is64;
        int s = load_idx(ei, e, is64);
        int d = load_idx(ei, E2v + e, is64);
        if ((unsigned)s < N2v && (unsigned)d < N2v) {
            float v = -w[e] * d_dinv2[s] * d_dinv2[d];
            int p = d_row2[d] + atomicAdd(&d_fill2[d], 1);
            if ((unsigned)p < E2v) { d_csrc2[p] = s; d_cval2[p] = v; }
        }
    }
}

// T1[0][n*60 + t*4 + b] = x[b, n, t]
__global__ void transpose_kernel(const float* __restrict__ x) {
    int i = blockIdx.x * 256 + threadIdx.x;
    if (i < T1_SLOT) {
        int n = i / D1v;
        int c = i - n * D1v;
        int t = c >> 2, b = c & 3;
        d_T1[i] = x[b * (N1v * Tv) + n * Tv + t];
    }
}

// ---------------- Chebyshev propagation (CSR gather; no atomics) ----------------
// T_1 = L_hat T_0 ; T_k = 2 L_hat T_{k-1} - T_{k-2}
__global__ void prop1_kernel(int k) {
    int n = blockIdx.x * 4 + threadIdx.y;
    int c = threadIdx.x;               // 0..63, active < 60
    const float* __restrict__ in = d_T1 + (k - 1) * T1_SLOT;
    int beg = d_row1[n], end = d_row1[n + 1];
    if (c < D1v) {
        float acc = 0.0f;
        for (int e = beg; e < end; e++)
            acc += d_cval1[e] * __ldg(&in[d_csrc1[e] * D1v + c]);
        float r;
        if (k == 1) r = acc;
        else        r = 2.0f * acc - d_T1[(k - 2) * T1_SLOT + n * D1v + c];
        d_T1[k * T1_SLOT + n * D1v + c] = r;
    }
}

__global__ void prop2_kernel(int k) {
    int n = blockIdx.x;
    int c = threadIdx.x;               // 0..255
    int b = c >> 6, d = c & 63;
    const float* __restrict__ in = d_T2g + (k - 1) * T2_SLOT + b * T2_BOFF;
    int beg = d_row2[n], end = d_row2[n + 1];
    float acc = 0.0f;
    for (int e = beg; e < end; e++)
        acc += d_cval2[e] * __ldg(&in[d_csrc2[e] * 64 + d]);
    float r;
    if (k == 1) r = acc;
    else        r = 2.0f * acc - d_T2g[(k - 2) * T2_SLOT + b * T2_BOFF + n * 64 + d];
    d_T2g[k * T2_SLOT + b * T2_BOFF + n * 64 + d] = r;
}

// ---------------- einsum 1: y1[n,g,b] = relu(b1[g] + sum_{k,t} T1[k][n,t,b] W1[k,t,g]) ----------------
__global__ void einsum1_kernel(const float* __restrict__ W1, const float* __restrict__ b1) {
    __shared__ __align__(16) float sW[Kv * Tv * G1v];   // 11520 floats = 46 KB
    for (int i = threadIdx.x; i < Kv * Tv * G1v; i += 64) sW[i] = W1[i];
    __syncthreads();
    int t = blockIdx.x * 64 + threadIdx.x;              // (n,b)
    int n = t >> 2, b = t & 3;
    float4 acc[16];
#pragma unroll
    for (int q = 0; q < 16; q++) acc[q] = make_float4(0.f, 0.f, 0.f, 0.f);
    for (int k = 0; k < Kv; k++) {
        const float* tp = d_T1 + k * T1_SLOT + n * D1v + b;
        const float* wp = sW + k * (Tv * G1v);
        for (int d = 0; d < Tv; d++) {
            float tv = __ldg(&tp[d * 4]);
            const float4* w4 = (const float4*)(wp + d * G1v);
#pragma unroll
            for (int q = 0; q < 16; q++) {
                float4 w = w4[q];
                acc[q].x += tv * w.x; acc[q].y += tv * w.y;
                acc[q].z += tv * w.z; acc[q].w += tv * w.w;
            }
        }
    }
    float* yp = d_y1 + n * 256 + b;
#pragma unroll
    for (int q = 0; q < 16; q++) {
        int g0 = q * 4;
        yp[(g0 + 0) * 4] = fmaxf(acc[q].x + b1[g0 + 0], 0.0f);
        yp[(g0 + 1) * 4] = fmaxf(acc[q].y + b1[g0 + 1], 0.0f);
        yp[(g0 + 2) * 4] = fmaxf(acc[q].z + b1[g0 + 2], 0.0f);
        yp[(g0 + 3) * 4] = fmaxf(acc[q].w + b1[g0 + 3], 0.0f);
    }
}

// ---------------- pooling GEMM: h2 = b_map(4096x8192) @ y1(8192x256) -> T2 slot0 [b][m][g] ----------------
// 128x128x16 smem tiles, 8x8 register micro-tiles, K-split=8 with atomic epilogue.
__global__ void pool_gemm_kernel(const float* __restrict__ A) {
    __shared__ __align__(16) float As[16 * 128];
    __shared__ __align__(16) float Bs[16 * 128];
    int tid = threadIdx.x;
    int n0 = blockIdx.x * 128;
    int m0 = blockIdx.y * 128;
    int kbeg = blockIdx.z * 1024;
    float acc[8][8];
#pragma unroll
    for (int i = 0; i < 8; i++)
#pragma unroll
        for (int j = 0; j < 8; j++) acc[i][j] = 0.0f;
    int ar = tid >> 2;          // 0..63
    int ac = (tid & 3) * 4;     // 0,4,8,12
    int br = tid >> 5;          // 0..7
    int bc = (tid & 31) * 4;    // 0..124
    int rx = tid & 15, ry = tid >> 4;
    for (int kt = 0; kt < 1024; kt += 16) {
        int k0 = kbeg + kt;
        float4 av0 = __ldg((const float4*)(A + (long long)(m0 + ar) * 8192 + k0 + ac));
        float4 av1 = __ldg((const float4*)(A + (long long)(m0 + ar + 64) * 8192 + k0 + ac));
        float4 bv0 = *(const float4*)(d_y1 + (k0 + br) * 256 + n0 + bc);
        float4 bv1 = *(const float4*)(d_y1 + (k0 + br + 8) * 256 + n0 + bc);
        __syncthreads();
        As[(ac + 0) * 128 + ar] = av0.x;
        As[(ac + 1) * 128 + ar] = av0.y;
        As[(ac + 2) * 128 + ar] = av0.z;
        As[(ac + 3) * 128 + ar] = av0.w;
        As[(ac + 0) * 128 + ar + 64] = av1.x;
        As[(ac + 1) * 128 + ar + 64] = av1.y;
        As[(ac + 2) * 128 + ar + 64] = av1.z;
        As[(ac + 3) * 128 + ar + 64] = av1.w;
        *(float4*)(Bs + br * 128 + bc) = bv0;
        *(float4*)(Bs + (br + 8) * 128 + bc) = bv1;
        __syncthreads();
#pragma unroll
        for (int kk = 0; kk < 16; kk++) {
            float a[8], bb[8];
            *(float4*)(a)      = *(const float4*)(As + kk * 128 + ry * 8);
            *(float4*)(a + 4)  = *(const float4*)(As + kk * 128 + ry * 8 + 4);
            *(float4*)(bb)     = *(const float4*)(Bs + kk * 128 + rx * 8);
            *(float4*)(bb + 4) = *(const float4*)(Bs + kk * 128 + rx * 8 + 4);
#pragma unroll
            for (int i = 0; i < 8; i++)
#pragma unroll
                for (int j = 0; j < 8; j++)
                    acc[i][j] += a[i] * bb[j];
        }
    }
#pragma unroll
    for (int i = 0; i < 8; i++) {
        int m = m0 + ry * 8 + i;
#pragma unroll
        for (int j = 0; j < 8; j++) {
            int col = n0 + rx * 8 + j;        // col = g*4 + b
            atomicAdd(&d_T2g[(col & 3) * T2_BOFF + m * 64 + (col >> 2)], acc[i][j]);
        }
    }
}

// ---------------- einsum 2: y2[n,g,b] = b2[g] + sum_{k,d} T2[k][b,n,d] W2[k,d,g] ----------------
__global__ void einsum2_kernel(const float* __restrict__ W2, const float* __restrict__ b2) {
    __shared__ __align__(16) float sW[64 * 32];
    int t = blockIdx.x * 64 + threadIdx.x;   // (n,b)
    int n = t >> 2, b = t & 3;
    float4 acc[8];
#pragma unroll
    for (int q = 0; q < 8; q++) acc[q] = make_float4(0.f, 0.f, 0.f, 0.f);
    for (int k = 0; k < Kv; k++) {
        __syncthreads();
        for (int i = threadIdx.x; i < 2048; i += 64) sW[i] = W2[k * 2048 + i];
        __syncthreads();
        const float* tp = d_T2g + k * T2_SLOT + b * T2_BOFF + n * 64;
        for (int d = 0; d < 64; d++) {
            float tv = __ldg(&tp[d]);
            const float4* w4 = (const float4*)(sW + d * 32);
#pragma unroll
            for (int q = 0; q < 8; q++) {
                float4 w = w4[q];
                acc[q].x += tv * w.x; acc[q].y += tv * w.y;
                acc[q].z += tv * w.z; acc[q].w += tv * w.w;
            }
        }
    }
    float* yp = d_y2 + n * 128 + b;
#pragma unroll
    for (int q = 0; q < 8; q++) {
        int g0 = q * 4;
        yp[(g0 + 0) * 4] = acc[q].x + b2[g0 + 0];
        yp[(g0 + 1) * 4] = acc[q].y + b2[g0 + 1];
        yp[(g0 + 2) * 4] = acc[q].z + b2[g0 + 2];
        yp[(g0 + 3) * 4] = acc[q].w + b2[g0 + 3];
    }
}

// ---------------- FC + log_softmax ----------------
// faithful torch .view(B,-1): flat[b, j] = y2_linear[b*131072 + j]  (y2 layout n*128+g*4+b)
__global__ void fc_kernel(const float* __restrict__ fcw, const float* __restrict__ fcb) {
    int bc = blockIdx.x;                 // 0..23 = b*6 + c
    int b = bc / 6, c = bc - b * 6;
    const float4* w4 = (const float4*)(fcw + (long long)c * 131072);
    const float4* h4 = (const float4*)(d_y2 + b * 131072);
    float s = 0.0f;
    for (int i = threadIdx.x; i < 32768; i += 256) {
        float4 a = __ldg(&w4[i]);
        float4 h = h4[i];
        s += a.x * h.x + a.y * h.y + a.z * h.z + a.w * h.w;
    }
    __shared__ float sh[256];
    sh[threadIdx.x] = s;
    __syncthreads();
    for (int off = 128; off > 0; off >>= 1) {
        if (threadIdx.x < off) sh[threadIdx.x] += sh[threadIdx.x + off];
        __syncthreads();
    }
    if (threadIdx.x == 0) d_logits[bc] = sh[0] + fcb[c];
}

__global__ void lsm_kernel(float* __restrict__ out) {
    int b = threadIdx.x;
    if (b < Bv) {
        float l[Cv];
        float m = -1e30f;
#pragma unroll
        for (int c = 0; c < Cv; c++) { l[c] = d_logits[b * Cv + c]; m = fmaxf(m, l[c]); }
        float s = 0.0f;
#pragma unroll
        for (int c = 0; c < Cv; c++) s += expf(l[c] - m);
        float L = logf(s);
#pragma unroll
        for (int c = 0; c < Cv; c++) out[b * Cv + c] = l[c] - m - L;
    }
}

// ---------------- launch ----------------
extern "C" void kernel_launch(void* const* d_in, const int* in_sizes, int n_in,
                              void* d_out, int out_size) {
    const float* x    = (const float*)d_in[0];
    const void*  ei1  = d_in[1];
    const float* ew1  = (const float*)d_in[2];
    const void*  ei2  = d_in[3];
    const float* ew2  = (const float*)d_in[4];
    const float* bmap = (const float*)d_in[5];
    const float* W1   = (const float*)d_in[6];
    const float* b1   = (const float*)d_in[7];
    const float* W2   = (const float*)d_in[8];
    const float* b2   = (const float*)d_in[9];
    const float* fcw  = (const float*)d_in[10];
    const float* fcb  = (const float*)d_in[11];
    float* out = (float*)d_out;

    detect_kernel<<<1, 32>>>((const int*)ei1);
    zero_kernel<<<T2_SLOT / 256, 256>>>();
    deg1_kernel<<<E1v / 256, 256>>>(ei1, ew1);
    deg2_kernel<<<E2v / 256, 256>>>(ei2, ew2);
    dinv_kernel<<<N1v / 256, 256>>>();
    scan_kernel<<<1, 1024>>>();
    fill1_kernel<<<E1v / 256, 256>>>(ei1, ew1);
    fill2_kernel<<<E2v / 256, 256>>>(ei2, ew2);
    transpose_kernel<<<T1_SLOT / 256, 256>>>(x);

    for (int k = 1; k < Kv; k++)
        prop1_kernel<<<N1v / 4, dim3(64, 4)>>>(k);
    einsum1_kernel<<<(N1v * Bv) / 64, 64>>>(W1, b1);

    pool_gemm_kernel<<<dim3(2, 32, 8), 256>>>(bmap);

    for (int k = 1; k < Kv; k++)
        prop2_kernel<<<N2v, 256>>>(k);
    einsum2_kernel<<<(N2v * Bv) / 64, 64>>>(W2, b2);

    fc_kernel<<<Bv * Cv, 256>>>(fcw, fcb);
    lsm_kernel<<<1, 32>>>(out);
}

// round 12
// speedup vs baseline: 1.3167x; 1.3167x over previous
#include <cuda_runtime.h>
#include <cuda_bf16.h>
#include <cstdint>

// ---------------- problem constants ----------------
#define N1v 8192
#define N2v 4096
#define Tv 15
#define Bv 4
#define E1v 131072
#define E2v 65536
#define Kv 12
#define G1v 64
#define G2v 32
#define Cv 6

#define D1v 60                    // T*B comps per node, layer1 (layout t*4+b)
#define T1_SLOT (N1v * D1v)       // 491520
#define T2_SLOT (N2v * 64 * Bv)   // 1048576, layout [b][n][g]
#define T2_BOFF (N2v * 64)        // 262144

// ---------------- scratch (device globals; allocation-free) ----------------
__device__ int   d_is64;
__device__ float d_deg1[N1v];
__device__ float d_dinv1[N1v];
__device__ float d_deg2[N2v];
__device__ float d_dinv2[N2v];
__device__ int   d_cnt1[N1v];
__device__ int   d_fill1[N1v];
__device__ int   d_row1[N1v + 1];
__device__ int   d_cnt2[N2v];
__device__ int   d_fill2[N2v];
__device__ int   d_row2[N2v + 1];
__device__ int   d_csrc1[E1v];
__device__ float d_cval1[E1v];
__device__ int   d_csrc2[E2v];
__device__ float d_cval2[E2v];
__device__ float d_T1[Kv * T1_SLOT];    // Cheb tensors layer1, [k][n*60 + t*4 + b]
__device__ float d_y1[N1v * 256];       // relu(conv1), [n*256 + g*4 + b]
__device__ unsigned short d_y1t_hi[256 * N1v];   // y1^T hi bf16, [col][k]
__device__ unsigned short d_y1t_lo[256 * N1v];   // y1^T lo bf16, [col][k]
__device__ float d_T2g[Kv * T2_SLOT];   // Cheb tensors layer2, [k][b][n][g]
__device__ float d_y2[N2v * 128];       // conv2 out, [n*128 + g*4 + b] (== torch flat order)
__device__ float d_logits[Bv * Cv];

// ================= warp-MMA helpers (baseline PTX; no 'a'-features) =================
__device__ __forceinline__ uint32_t smem_to_u32(const void* smem_ptr) {
    uint32_t addr;
    asm("{ .reg .u64 tmp; cvta.to.shared.u64 tmp, %1; cvt.u32.u64 %0, tmp; }"
        : "=r"(addr) : "l"(smem_ptr));
    return addr;
}
__device__ __forceinline__ void ldsm_x4(uint32_t* r, uint32_t addr) {
    asm volatile("ldmatrix.sync.aligned.m8n8.x4.shared.b16 {%0,%1,%2,%3}, [%4];"
        : "=r"(r[0]), "=r"(r[1]), "=r"(r[2]), "=r"(r[3]) : "r"(addr));
}
__device__ __forceinline__ void ldsm_x2(uint32_t* r, uint32_t addr) {
    asm volatile("ldmatrix.sync.aligned.m8n8.x2.shared.b16 {%0,%1}, [%2];"
        : "=r"(r[0]), "=r"(r[1]) : "r"(addr));
}
__device__ __forceinline__ void mma_bf16(float* c, const uint32_t* a, const uint32_t* b) {
    asm volatile(
        "mma.sync.aligned.m16n8k16.row.col.f32.bf16.bf16.f32 "
        "{%0,%1,%2,%3}, {%4,%5,%6,%7}, {%8,%9}, {%0,%1,%2,%3};"
        : "+f"(c[0]), "+f"(c[1]), "+f"(c[2]), "+f"(c[3])
        : "r"(a[0]), "r"(a[1]), "r"(a[2]), "r"(a[3]), "r"(b[0]), "r"(b[1]));
}

// ---------------- dtype detection for edge indices ----------------
__global__ void detect_kernel(const int* __restrict__ ei1_as_i32) {
    if (threadIdx.x == 0) {
        int is64 = 1;
        for (int i = 1; i < 64; i += 2)
            if (ei1_as_i32[i] != 0) { is64 = 0; break; }
        d_is64 = is64;
    }
}
__device__ __forceinline__ int load_idx(const void* ei, int pos, int is64) {
    if (is64) return (int)((const long long*)ei)[pos];
    return ((const int*)ei)[pos];
}

// ---------------- init / graph normalization ----------------
__global__ void zero_kernel() {
    int i = blockIdx.x * 256 + threadIdx.x;
    if (i < T2_SLOT) d_T2g[i] = 0.0f;
    if (i < N1v) { d_deg1[i] = 0.0f; d_cnt1[i] = 0; d_fill1[i] = 0; }
    if (i < N2v) { d_deg2[i] = 0.0f; d_cnt2[i] = 0; d_fill2[i] = 0; }
}

__global__ void deg1_kernel(const void* __restrict__ ei, const float* __restrict__ w) {
    int e = blockIdx.x * 256 + threadIdx.x;
    if (e < E1v) {
        int is64 = d_is64;
        int d = load_idx(ei, E1v + e, is64);
        if ((unsigned)d < N1v) { atomicAdd(&d_deg1[d], w[e]); atomicAdd(&d_cnt1[d], 1); }
    }
}
__global__ void deg2_kernel(const void* __restrict__ ei, const float* __restrict__ w) {
    int e = blockIdx.x * 256 + threadIdx.x;
    if (e < E2v) {
        int is64 = d_is64;
        int d = load_idx(ei, E2v + e, is64);
        if ((unsigned)d < N2v) { atomicAdd(&d_deg2[d], w[e]); atomicAdd(&d_cnt2[d], 1); }
    }
}

__global__ void dinv_kernel() {
    int i = blockIdx.x * 256 + threadIdx.x;
    if (i < N1v) { float v = d_deg1[i]; d_dinv1[i] = (v > 0.0f) ? rsqrtf(v) : 0.0f; }
    if (i < N2v) { float v = d_deg2[i]; d_dinv2[i] = (v > 0.0f) ? rsqrtf(v) : 0.0f; }
}

__global__ void scan_kernel() {
    __shared__ int sh[1024];
    int tid = threadIdx.x;
    {
        int v[8]; int s = 0;
#pragma unroll
        for (int j = 0; j < 8; j++) { v[j] = d_cnt1[tid * 8 + j]; s += v[j]; }
        sh[tid] = s; __syncthreads();
        for (int off = 1; off < 1024; off <<= 1) {
            int x = (tid >= off) ? sh[tid - off] : 0;
            __syncthreads();
            sh[tid] += x;
            __syncthreads();
        }
        int run = sh[tid] - s;
#pragma unroll
        for (int j = 0; j < 8; j++) { d_row1[tid * 8 + j] = run; run += v[j]; }
        if (tid == 1023) d_row1[N1v] = run;
    }
    __syncthreads();
    {
        int v[4]; int s = 0;
#pragma unroll
        for (int j = 0; j < 4; j++) { v[j] = d_cnt2[tid * 4 + j]; s += v[j]; }
        sh[tid] = s; __syncthreads();
        for (int off = 1; off < 1024; off <<= 1) {
            int x = (tid >= off) ? sh[tid - off] : 0;
            __syncthreads();
            sh[tid] += x;
            __syncthreads();
        }
        int run = sh[tid] - s;
#pragma unroll
        for (int j = 0; j < 4; j++) { d_row2[tid * 4 + j] = run; run += v[j]; }
        if (tid == 1023) d_row2[N2v] = run;
    }
}

__global__ void fill1_kernel(const void* __restrict__ ei, const float* __restrict__ w) {
    int e = blockIdx.x * 256 + threadIdx.x;
    if (e < E1v) {
        int is64 = d_is64;
        int s = load_idx(ei, e, is64);
        int d = load_idx(ei, E1v + e, is64);
        if ((unsigned)s < N1v && (unsigned)d < N1v) {
            float v = -w[e] * d_dinv1[s] * d_dinv1[d];
            int p = d_row1[d] + atomicAdd(&d_fill1[d], 1);
            if ((unsigned)p < E1v) { d_csrc1[p] = s; d_cval1[p] = v; }
        }
    }
}
__global__ void fill2_kernel(const void* __restrict__ ei, const float* __restrict__ w) {
    int e = blockIdx.x * 256 + threadIdx.x;
    if (e < E2v) {
        int is64 = d_is64;
        int s = load_idx(ei, e, is64);
        int d = load_idx(ei, E2v + e, is64);
        if ((unsigned)s < N2v && (unsigned)d < N2v) {
            float v = -w[e] * d_dinv2[s] * d_dinv2[d];
            int p = d_row2[d] + atomicAdd(&d_fill2[d], 1);
            if ((unsigned)p < E2v) { d_csrc2[p] = s; d_cval2[p] = v; }
        }
    }
}

__global__ void transpose_kernel(const float* __restrict__ x) {
    int i = blockIdx.x * 256 + threadIdx.x;
    if (i < T1_SLOT) {
        int n = i / D1v;
        int c = i - n * D1v;
        int t = c >> 2, b = c & 3;
        d_T1[i] = x[b * (N1v * Tv) + n * Tv + t];
    }
}

// ---------------- Chebyshev propagation (CSR gather; no atomics) ----------------
__global__ void prop1_kernel(int k) {
    int n = blockIdx.x * 4 + threadIdx.y;
    int c = threadIdx.x;
    const float* __restrict__ in = d_T1 + (k - 1) * T1_SLOT;
    int beg = d_row1[n], end = d_row1[n + 1];
    if (c < D1v) {
        float acc = 0.0f;
        for (int e = beg; e < end; e++)
            acc += d_cval1[e] * __ldg(&in[d_csrc1[e] * D1v + c]);
        float r;
        if (k == 1) r = acc;
        else        r = 2.0f * acc - d_T1[(k - 2) * T1_SLOT + n * D1v + c];
        d_T1[k * T1_SLOT + n * D1v + c] = r;
    }
}

__global__ void prop2_kernel(int k) {
    int n = blockIdx.x;
    int c = threadIdx.x;
    int b = c >> 6, d = c & 63;
    const float* __restrict__ in = d_T2g + (k - 1) * T2_SLOT + b * T2_BOFF;
    int beg = d_row2[n], end = d_row2[n + 1];
    float acc = 0.0f;
    for (int e = beg; e < end; e++)
        acc += d_cval2[e] * __ldg(&in[d_csrc2[e] * 64 + d]);
    float r;
    if (k == 1) r = acc;
    else        r = 2.0f * acc - d_T2g[(k - 2) * T2_SLOT + b * T2_BOFF + n * 64 + d];
    d_T2g[k * T2_SLOT + b * T2_BOFF + n * 64 + d] = r;
}

// ---------------- einsum 1 ----------------
__global__ void einsum1_kernel(const float* __restrict__ W1, const float* __restrict__ b1) {
    __shared__ __align__(16) float sW[Kv * Tv * G1v];
    for (int i = threadIdx.x; i < Kv * Tv * G1v; i += 64) sW[i] = W1[i];
    __syncthreads();
    int t = blockIdx.x * 64 + threadIdx.x;
    int n = t >> 2, b = t & 3;
    float4 acc[16];
#pragma unroll
    for (int q = 0; q < 16; q++) acc[q] = make_float4(0.f, 0.f, 0.f, 0.f);
    for (int k = 0; k < Kv; k++) {
        const float* tp = d_T1 + k * T1_SLOT + n * D1v + b;
        const float* wp = sW + k * (Tv * G1v);
        for (int d = 0; d < Tv; d++) {
            float tv = __ldg(&tp[d * 4]);
            const float4* w4 = (const float4*)(wp + d * G1v);
#pragma unroll
            for (int q = 0; q < 16; q++) {
                float4 w = w4[q];
                acc[q].x += tv * w.x; acc[q].y += tv * w.y;
                acc[q].z += tv * w.z; acc[q].w += tv * w.w;
            }
        }
    }
    float* yp = d_y1 + n * 256 + b;
#pragma unroll
    for (int q = 0; q < 16; q++) {
        int g0 = q * 4;
        yp[(g0 + 0) * 4] = fmaxf(acc[q].x + b1[g0 + 0], 0.0f);
        yp[(g0 + 1) * 4] = fmaxf(acc[q].y + b1[g0 + 1], 0.0f);
        yp[(g0 + 2) * 4] = fmaxf(acc[q].z + b1[g0 + 2], 0.0f);
        yp[(g0 + 3) * 4] = fmaxf(acc[q].w + b1[g0 + 3], 0.0f);
    }
}

// ---------------- y1 -> transposed bf16 hi/lo split ----------------
__global__ void y1split_kernel() {
    __shared__ float tile[32][33];
    int k0 = blockIdx.x * 32, c0 = blockIdx.y * 32;
    int tx = threadIdx.x, ty = threadIdx.y;   // 32 x 8
#pragma unroll
    for (int i = 0; i < 4; i++)
        tile[ty + 8 * i][tx] = d_y1[(k0 + ty + 8 * i) * 256 + c0 + tx];
    __syncthreads();
#pragma unroll
    for (int i = 0; i < 4; i++) {
        int c = c0 + ty + 8 * i;
        float v = tile[tx][ty + 8 * i];
        __nv_bfloat16 h = __float2bfloat16(v);
        float lo = v - __bfloat162float(h);
        long long idx = (long long)c * N1v + k0 + tx;
        d_y1t_hi[idx] = __bfloat16_as_ushort(h);
        d_y1t_lo[idx] = __bfloat16_as_ushort(__float2bfloat16(lo));
    }
}

// ---------------- warp-MMA pooling GEMM ----------------
// C[4096,256] = b_map @ y1, bf16 3-term split (hi*hi + lo*hi + hi*lo), fp32 acc.
// CTA tile 128x128, KB=64, double-buffered smem, grid (KSPLIT=2, 32, 2).
#define KSPLIT 2
#define KB2 64
#define ASTRIDE 72                    // bf16 units per smem row (64 + 8 pad)
#define MAT_BYTES (128 * ASTRIDE * 2) // 18432
#define STAGE_BYTES (4 * MAT_BYTES)   // 73728
#define SMG_A_HI(s) ((s) * STAGE_BYTES)
#define SMG_A_LO(s) ((s) * STAGE_BYTES + MAT_BYTES)
#define SMG_B_HI(s) ((s) * STAGE_BYTES + 2 * MAT_BYTES)
#define SMG_B_LO(s) ((s) * STAGE_BYTES + 3 * MAT_BYTES)
#define SMEM_GEMM_TOTAL (2 * STAGE_BYTES)   // 147456

__device__ __forceinline__ uint32_t pack_bf2(__nv_bfloat16 a, __nv_bfloat16 b) {
    return ((uint32_t)__bfloat16_as_ushort(b) << 16) | (uint32_t)__bfloat16_as_ushort(a);
}

__device__ __forceinline__ void fill_stage(char* smem, int s, const float* __restrict__ A,
                                           int m0, int n0, int kblk) {
    int t = threadIdx.x;
    char* ah = smem + SMG_A_HI(s);
    char* al = smem + SMG_A_LO(s);
    char* bh = smem + SMG_B_HI(s);
    char* bl = smem + SMG_B_LO(s);
    // A: 128 rows x 64 fp32 -> bf16 hi/lo
#pragma unroll
    for (int i = 0; i < 8; i++) {
        int f = t + 256 * i;              // 0..2047 float4s
        int r = f >> 4, c4 = (f & 15) * 4;
        float4 v = __ldg((const float4*)(A + (long long)(m0 + r) * 8192 + kblk + c4));
        __nv_bfloat16 h0 = __float2bfloat16(v.x);
        __nv_bfloat16 h1 = __float2bfloat16(v.y);
        __nv_bfloat16 h2 = __float2bfloat16(v.z);
        __nv_bfloat16 h3 = __float2bfloat16(v.w);
        __nv_bfloat16 l0 = __float2bfloat16(v.x - __bfloat162float(h0));
        __nv_bfloat16 l1 = __float2bfloat16(v.y - __bfloat162float(h1));
        __nv_bfloat16 l2 = __float2bfloat16(v.z - __bfloat162float(h2));
        __nv_bfloat16 l3 = __float2bfloat16(v.w - __bfloat162float(h3));
        int off = (r * ASTRIDE + c4) * 2;   // bytes, 8B-aligned
        *(uint2*)(ah + off) = make_uint2(pack_bf2(h0, h1), pack_bf2(h2, h3));
        *(uint2*)(al + off) = make_uint2(pack_bf2(l0, l1), pack_bf2(l2, l3));
    }
    // B: 128 n-rows x 64 bf16 (pre-split), [col][k] K-major in gmem
#pragma unroll
    for (int i = 0; i < 4; i++) {
        int f = t + 256 * i;              // 0..1023 float4s
        int r = f >> 3, c8 = (f & 7) * 8;
        long long src = ((long long)(n0 + r) * N1v + kblk + c8) * 2;   // byte offset
        int off = (r * ASTRIDE + c8) * 2;   // bytes, 16B-aligned
        *(float4*)(bh + off) = *(const float4*)((const char*)d_y1t_hi + src);
        *(float4*)(bl + off) = *(const float4*)((const char*)d_y1t_lo + src);
    }
}

__global__ void __launch_bounds__(256, 1) pool_gemm_mma(const float* __restrict__ A) {
    extern __shared__ __align__(16) char smem[];
    uint32_t sbase = smem_to_u32(smem);
    int tid = threadIdx.x, wid = tid >> 5, lid = tid & 31;
    int m0 = blockIdx.y * 128, n0 = blockIdx.z * 128;
    int kbase = blockIdx.x * (N1v / KSPLIT);
    const int NB = (N1v / KSPLIT) / KB2;      // 32
    int wm = (wid >> 1) * 32;                 // warp m offset within CTA (0..96)
    int wn = (wid & 1) * 64;                  // warp n offset within CTA (0,64)

    float acc[2][8][4];
#pragma unroll
    for (int mt = 0; mt < 2; mt++)
#pragma unroll
        for (int nt = 0; nt < 8; nt++)
#pragma unroll
            for (int q = 0; q < 4; q++) acc[mt][nt][q] = 0.0f;

    // per-lane ldmatrix row/col selectors
    int arow = wm + (lid & 15);
    int acol = (lid >> 4) * 8;
    int l16 = lid & 15;
    int brow = wn + (l16 & 7);
    int bcol = ((l16 >> 3) & 1) * 8;

    fill_stage(smem, 0, A, m0, n0, kbase);
    __syncthreads();

    for (int it = 0; it < NB; it++) {
        if (it + 1 < NB)
            fill_stage(smem, (it + 1) & 1, A, m0, n0, kbase + (it + 1) * KB2);
        int s = it & 1;
        uint32_t aHiB = sbase + SMG_A_HI(s), aLoB = sbase + SMG_A_LO(s);
        uint32_t bHiB = sbase + SMG_B_HI(s), bLoB = sbase + SMG_B_LO(s);
#pragma unroll
        for (int k16 = 0; k16 < KB2 / 16; k16++) {
            uint32_t ah[2][4], alo[2][4], bhf[8][2], blf[8][2];
#pragma unroll
            for (int mt = 0; mt < 2; mt++) {
                uint32_t off = (uint32_t)(((arow + mt * 16) * ASTRIDE + k16 * 16 + acol) * 2);
                ldsm_x4(ah[mt],  aHiB + off);
                ldsm_x4(alo[mt], aLoB + off);
            }
#pragma unroll
            for (int nt = 0; nt < 8; nt++) {
                uint32_t off = (uint32_t)(((brow + nt * 8) * ASTRIDE + k16 * 16 + bcol) * 2);
                ldsm_x2(bhf[nt], bHiB + off);
                ldsm_x2(blf[nt], bLoB + off);
            }
#pragma unroll
            for (int mt = 0; mt < 2; mt++)
#pragma unroll
                for (int nt = 0; nt < 8; nt++) {
                    mma_bf16(acc[mt][nt], ah[mt],  bhf[nt]);
                    mma_bf16(acc[mt][nt], alo[mt], bhf[nt]);
                    mma_bf16(acc[mt][nt], ah[mt],  blf[nt]);
                }
        }
        __syncthreads();
    }

    // epilogue: atomic-accumulate into d_T2g slot 0 ([b][m][g], col = g*4+b)
#pragma unroll
    for (int mt = 0; mt < 2; mt++) {
        int m_lo = m0 + wm + mt * 16 + (lid >> 2);
        int m_hi = m_lo + 8;
#pragma unroll
        for (int nt = 0; nt < 8; nt++) {
            int c0 = n0 + wn + nt * 8 + (lid & 3) * 2;
            int c1 = c0 + 1;
            atomicAdd(&d_T2g[(c0 & 3) * T2_BOFF + m_lo * 64 + (c0 >> 2)], acc[mt][nt][0]);
            atomicAdd(&d_T2g[(c1 & 3) * T2_BOFF + m_lo * 64 + (c1 >> 2)], acc[mt][nt][1]);
            atomicAdd(&d_T2g[(c0 & 3) * T2_BOFF + m_hi * 64 + (c0 >> 2)], acc[mt][nt][2]);
            atomicAdd(&d_T2g[(c1 & 3) * T2_BOFF + m_hi * 64 + (c1 >> 2)], acc[mt][nt][3]);
        }
    }
}

// ---------------- einsum 2 ----------------
__global__ void einsum2_kernel(const float* __restrict__ W2, const float* __restrict__ b2) {
    __shared__ __align__(16) float sW[64 * 32];
    int t = blockIdx.x * 64 + threadIdx.x;
    int n = t >> 2, b = t & 3;
    float4 acc[8];
#pragma unroll
    for (int q = 0; q < 8; q++) acc[q] = make_float4(0.f, 0.f, 0.f, 0.f);
    for (int k = 0; k < Kv; k++) {
        __syncthreads();
        for (int i = threadIdx.x; i < 2048; i += 64) sW[i] = W2[k * 2048 + i];
        __syncthreads();
        const float* tp = d_T2g + k * T2_SLOT + b * T2_BOFF + n * 64;
        for (int d = 0; d < 64; d++) {
            float tv = __ldg(&tp[d]);
            const float4* w4 = (const float4*)(sW + d * 32);
#pragma unroll
            for (int q = 0; q < 8; q++) {
                float4 w = w4[q];
                acc[q].x += tv * w.x; acc[q].y += tv * w.y;
                acc[q].z += tv * w.z; acc[q].w += tv * w.w;
            }
        }
    }
    float* yp = d_y2 + n * 128 + b;
#pragma unroll
    for (int q = 0; q < 8; q++) {
        int g0 = q * 4;
        yp[(g0 + 0) * 4] = acc[q].x + b2[g0 + 0];
        yp[(g0 + 1) * 4] = acc[q].y + b2[g0 + 1];
        yp[(g0 + 2) * 4] = acc[q].z + b2[g0 + 2];
        yp[(g0 + 3) * 4] = acc[q].w + b2[g0 + 3];
    }
}

// ---------------- FC + log_softmax ----------------
__global__ void fc_kernel(const float* __restrict__ fcw, const float* __restrict__ fcb) {
    int bc = blockIdx.x;
    int b = bc / 6, c = bc - b * 6;
    const float4* w4 = (const float4*)(fcw + (long long)c * 131072);
    const float4* h4 = (const float4*)(d_y2 + b * 131072);
    float s = 0.0f;
    for (int i = threadIdx.x; i < 32768; i += 256) {
        float4 a = __ldg(&w4[i]);
        float4 h = h4[i];
        s += a.x * h.x + a.y * h.y + a.z * h.z + a.w * h.w;
    }
    __shared__ float sh[256];
    sh[threadIdx.x] = s;
    __syncthreads();
    for (int off = 128; off > 0; off >>= 1) {
        if (threadIdx.x < off) sh[threadIdx.x] += sh[threadIdx.x + off];
        __syncthreads();
    }
    if (threadIdx.x == 0) d_logits[bc] = sh[0] + fcb[c];
}

__global__ void lsm_kernel(float* __restrict__ out) {
    int b = threadIdx.x;
    if (b < Bv) {
        float l[Cv];
        float m = -1e30f;
#pragma unroll
        for (int c = 0; c < Cv; c++) { l[c] = d_logits[b * Cv + c]; m = fmaxf(m, l[c]); }
        float s = 0.0f;
#pragma unroll
        for (int c = 0; c < Cv; c++) s += expf(l[c] - m);
        float L = logf(s);
#pragma unroll
        for (int c = 0; c < Cv; c++) out[b * Cv + c] = l[c] - m - L;
    }
}

// ---------------- launch ----------------
extern "C" void kernel_launch(void* const* d_in, const int* in_sizes, int n_in,
                              void* d_out, int out_size) {
    const float* x    = (const float*)d_in[0];
    const void*  ei1  = d_in[1];
    const float* ew1  = (const float*)d_in[2];
    const void*  ei2  = d_in[3];
    const float* ew2  = (const float*)d_in[4];
    const float* bmap = (const float*)d_in[5];
    const float* W1   = (const float*)d_in[6];
    const float* b1   = (const float*)d_in[7];
    const float* W2   = (const float*)d_in[8];
    const float* b2   = (const float*)d_in[9];
    const float* fcw  = (const float*)d_in[10];
    const float* fcb  = (const float*)d_in[11];
    float* out = (float*)d_out;

    cudaFuncSetAttribute(pool_gemm_mma, cudaFuncAttributeMaxDynamicSharedMemorySize,
                         SMEM_GEMM_TOTAL);

    detect_kernel<<<1, 32>>>((const int*)ei1);
    zero_kernel<<<T2_SLOT / 256, 256>>>();
    deg1_kernel<<<E1v / 256, 256>>>(ei1, ew1);
    deg2_kernel<<<E2v / 256, 256>>>(ei2, ew2);
    dinv_kernel<<<N1v / 256, 256>>>();
    scan_kernel<<<1, 1024>>>();
    fill1_kernel<<<E1v / 256, 256>>>(ei1, ew1);
    fill2_kernel<<<E2v / 256, 256>>>(ei2, ew2);
    transpose_kernel<<<T1_SLOT / 256, 256>>>(x);

    for (int k = 1; k < Kv; k++)
        prop1_kernel<<<N1v / 4, dim3(64, 4)>>>(k);
    einsum1_kernel<<<(N1v * Bv) / 64, 64>>>(W1, b1);

    y1split_kernel<<<dim3(N1v / 32, 256 / 32), dim3(32, 8)>>>();
    pool_gemm_mma<<<dim3(KSPLIT, 32, 2), 256, SMEM_GEMM_TOTAL>>>(bmap);

    for (int k = 1; k < Kv; k++)
        prop2_kernel<<<N2v, 256>>>(k);
    einsum2_kernel<<<(N2v * Bv) / 64, 64>>>(W2, b2);

    fc_kernel<<<Bv * Cv, 256>>>(fcw, fcb);
    lsm_kernel<<<1, 32>>>(out);
}

// round 13
// speedup vs baseline: 1.4181x; 1.0770x over previous
#include <cuda_runtime.h>
#include <cuda_bf16.h>
#include <cstdint>

// ---------------- problem constants ----------------
#define N1v 8192
#define N2v 4096
#define Tv 15
#define Bv 4
#define E1v 131072
#define E2v 65536
#define Kv 12
#define G1v 64
#define G2v 32
#define Cv 6

#define D1v 60                    // T*B comps per node, layer1 (layout t*4+b)
#define T1_SLOT (N1v * D1v)       // 491520
#define T2_SLOT (N2v * 64 * Bv)   // 1048576, layout [b][n][g]
#define T2_BOFF (N2v * 64)        // 262144

// ---------------- scratch (device globals; allocation-free) ----------------
__device__ int   d_is64;
__device__ float d_deg1[N1v];
__device__ float d_dinv1[N1v];
__device__ float d_deg2[N2v];
__device__ float d_dinv2[N2v];
__device__ int   d_cnt1[N1v];
__device__ int   d_fill1[N1v];
__device__ int   d_row1[N1v + 1];
__device__ int   d_cnt2[N2v];
__device__ int   d_fill2[N2v];
__device__ int   d_row2[N2v + 1];
__device__ int   d_csrc1[E1v];
__device__ float d_cval1[E1v];
__device__ int   d_csrc2[E2v];
__device__ float d_cval2[E2v];
__device__ float d_T1[Kv * T1_SLOT];    // Cheb tensors layer1, [k][n*60 + t*4 + b]
__device__ float d_y1[N1v * 256];       // relu(conv1), [n*256 + g*4 + b]
__device__ unsigned short d_y1t_hi[256 * N1v];   // y1^T hi bf16, [col][k]
__device__ unsigned short d_y1t_lo[256 * N1v];   // y1^T lo bf16, [col][k]
__device__ unsigned short d_A_hi[(long long)N2v * N1v];   // b_map hi bf16, 64MB
__device__ unsigned short d_A_lo[(long long)N2v * N1v];   // b_map lo bf16, 64MB
__device__ float d_T2g[Kv * T2_SLOT];   // Cheb tensors layer2, [k][b][n][g]
__device__ float d_y2[N2v * 128];       // conv2 out, [n*128 + g*4 + b] (== torch flat order)
__device__ float d_logits[Bv * Cv];

// ================= warp-MMA / cp.async helpers (baseline PTX) =================
__device__ __forceinline__ uint32_t smem_to_u32(const void* smem_ptr) {
    uint32_t addr;
    asm("{ .reg .u64 tmp; cvta.to.shared.u64 tmp, %1; cvt.u32.u64 %0, tmp; }"
        : "=r"(addr) : "l"(smem_ptr));
    return addr;
}
__device__ __forceinline__ void ldsm_x4(uint32_t* r, uint32_t addr) {
    asm volatile("ldmatrix.sync.aligned.m8n8.x4.shared.b16 {%0,%1,%2,%3}, [%4];"
        : "=r"(r[0]), "=r"(r[1]), "=r"(r[2]), "=r"(r[3]) : "r"(addr));
}
__device__ __forceinline__ void ldsm_x2(uint32_t* r, uint32_t addr) {
    asm volatile("ldmatrix.sync.aligned.m8n8.x2.shared.b16 {%0,%1}, [%2];"
        : "=r"(r[0]), "=r"(r[1]) : "r"(addr));
}
__device__ __forceinline__ void mma_bf16(float* c, const uint32_t* a, const uint32_t* b) {
    asm volatile(
        "mma.sync.aligned.m16n8k16.row.col.f32.bf16.bf16.f32 "
        "{%0,%1,%2,%3}, {%4,%5,%6,%7}, {%8,%9}, {%0,%1,%2,%3};"
        : "+f"(c[0]), "+f"(c[1]), "+f"(c[2]), "+f"(c[3])
        : "r"(a[0]), "r"(a[1]), "r"(a[2]), "r"(a[3]), "r"(b[0]), "r"(b[1]));
}
__device__ __forceinline__ void cp16(uint32_t s, const void* g) {
    asm volatile("cp.async.cg.shared.global [%0], [%1], 16;" :: "r"(s), "l"(g) : "memory");
}
#define CP_COMMIT() asm volatile("cp.async.commit_group;" ::: "memory")
#define CP_WAIT2()  asm volatile("cp.async.wait_group 2;" ::: "memory")

// ---------------- dtype detection for edge indices ----------------
__global__ void detect_kernel(const int* __restrict__ ei1_as_i32) {
    if (threadIdx.x == 0) {
        int is64 = 1;
        for (int i = 1; i < 64; i += 2)
            if (ei1_as_i32[i] != 0) { is64 = 0; break; }
        d_is64 = is64;
    }
}
__device__ __forceinline__ int load_idx(const void* ei, int pos, int is64) {
    if (is64) return (int)((const long long*)ei)[pos];
    return ((const int*)ei)[pos];
}

// ---------------- init / graph normalization ----------------
__global__ void zero_kernel() {
    int i = blockIdx.x * 256 + threadIdx.x;
    if (i < T2_SLOT) d_T2g[i] = 0.0f;
    if (i < N1v) { d_deg1[i] = 0.0f; d_cnt1[i] = 0; d_fill1[i] = 0; }
    if (i < N2v) { d_deg2[i] = 0.0f; d_cnt2[i] = 0; d_fill2[i] = 0; }
    if (i < Bv * Cv) d_logits[i] = 0.0f;
}

__global__ void deg1_kernel(const void* __restrict__ ei, const float* __restrict__ w) {
    int e = blockIdx.x * 256 + threadIdx.x;
    if (e < E1v) {
        int is64 = d_is64;
        int d = load_idx(ei, E1v + e, is64);
        if ((unsigned)d < N1v) { atomicAdd(&d_deg1[d], w[e]); atomicAdd(&d_cnt1[d], 1); }
    }
}
__global__ void deg2_kernel(const void* __restrict__ ei, const float* __restrict__ w) {
    int e = blockIdx.x * 256 + threadIdx.x;
    if (e < E2v) {
        int is64 = d_is64;
        int d = load_idx(ei, E2v + e, is64);
        if ((unsigned)d < N2v) { atomicAdd(&d_deg2[d], w[e]); atomicAdd(&d_cnt2[d], 1); }
    }
}

__global__ void dinv_kernel() {
    int i = blockIdx.x * 256 + threadIdx.x;
    if (i < N1v) { float v = d_deg1[i]; d_dinv1[i] = (v > 0.0f) ? rsqrtf(v) : 0.0f; }
    if (i < N2v) { float v = d_deg2[i]; d_dinv2[i] = (v > 0.0f) ? rsqrtf(v) : 0.0f; }
}

__global__ void scan_kernel() {
    __shared__ int sh[1024];
    int tid = threadIdx.x;
    {
        int v[8]; int s = 0;
#pragma unroll
        for (int j = 0; j < 8; j++) { v[j] = d_cnt1[tid * 8 + j]; s += v[j]; }
        sh[tid] = s; __syncthreads();
        for (int off = 1; off < 1024; off <<= 1) {
            int x = (tid >= off) ? sh[tid - off] : 0;
            __syncthreads();
            sh[tid] += x;
            __syncthreads();
        }
        int run = sh[tid] - s;
#pragma unroll
        for (int j = 0; j < 8; j++) { d_row1[tid * 8 + j] = run; run += v[j]; }
        if (tid == 1023) d_row1[N1v] = run;
    }
    __syncthreads();
    {
        int v[4]; int s = 0;
#pragma unroll
        for (int j = 0; j < 4; j++) { v[j] = d_cnt2[tid * 4 + j]; s += v[j]; }
        sh[tid] = s; __syncthreads();
        for (int off = 1; off < 1024; off <<= 1) {
            int x = (tid >= off) ? sh[tid - off] : 0;
            __syncthreads();
            sh[tid] += x;
            __syncthreads();
        }
        int run = sh[tid] - s;
#pragma unroll
        for (int j = 0; j < 4; j++) { d_row2[tid * 4 + j] = run; run += v[j]; }
        if (tid == 1023) d_row2[N2v] = run;
    }
}

__global__ void fill1_kernel(const void* __restrict__ ei, const float* __restrict__ w) {
    int e = blockIdx.x * 256 + threadIdx.x;
    if (e < E1v) {
        int is64 = d_is64;
        int s = load_idx(ei, e, is64);
        int d = load_idx(ei, E1v + e, is64);
        if ((unsigned)s < N1v && (unsigned)d < N1v) {
            float v = -w[e] * d_dinv1[s] * d_dinv1[d];
            int p = d_row1[d] + atomicAdd(&d_fill1[d], 1);
            if ((unsigned)p < E1v) { d_csrc1[p] = s; d_cval1[p] = v; }
        }
    }
}
__global__ void fill2_kernel(const void* __restrict__ ei, const float* __restrict__ w) {
    int e = blockIdx.x * 256 + threadIdx.x;
    if (e < E2v) {
        int is64 = d_is64;
        int s = load_idx(ei, e, is64);
        int d = load_idx(ei, E2v + e, is64);
        if ((unsigned)s < N2v && (unsigned)d < N2v) {
            float v = -w[e] * d_dinv2[s] * d_dinv2[d];
            int p = d_row2[d] + atomicAdd(&d_fill2[d], 1);
            if ((unsigned)p < E2v) { d_csrc2[p] = s; d_cval2[p] = v; }
        }
    }
}

__global__ void transpose_kernel(const float* __restrict__ x) {
    int i = blockIdx.x * 256 + threadIdx.x;
    if (i < T1_SLOT) {
        int n = i / D1v;
        int c = i - n * D1v;
        int t = c >> 2, b = c & 3;
        d_T1[i] = x[b * (N1v * Tv) + n * Tv + t];
    }
}

__device__ __forceinline__ uint32_t pack_bf2(__nv_bfloat16 a, __nv_bfloat16 b) {
    return ((uint32_t)__bfloat16_as_ushort(b) << 16) | (uint32_t)__bfloat16_as_ushort(a);
}

// ---------------- b_map -> bf16 hi/lo (one pass, HBM-bound) ----------------
__global__ void aconv_kernel(const float* __restrict__ A) {
    long long i = ((long long)blockIdx.x * 256 + threadIdx.x) * 4;
    float4 v = __ldg((const float4*)(A + i));
    __nv_bfloat16 h0 = __float2bfloat16(v.x);
    __nv_bfloat16 h1 = __float2bfloat16(v.y);
    __nv_bfloat16 h2 = __float2bfloat16(v.z);
    __nv_bfloat16 h3 = __float2bfloat16(v.w);
    __nv_bfloat16 l0 = __float2bfloat16(v.x - __bfloat162float(h0));
    __nv_bfloat16 l1 = __float2bfloat16(v.y - __bfloat162float(h1));
    __nv_bfloat16 l2 = __float2bfloat16(v.z - __bfloat162float(h2));
    __nv_bfloat16 l3 = __float2bfloat16(v.w - __bfloat162float(h3));
    *(uint2*)((char*)d_A_hi + i * 2) = make_uint2(pack_bf2(h0, h1), pack_bf2(h2, h3));
    *(uint2*)((char*)d_A_lo + i * 2) = make_uint2(pack_bf2(l0, l1), pack_bf2(l2, l3));
}

// ---------------- Chebyshev propagation (CSR gather; no atomics) ----------------
__global__ void prop1_kernel(int k) {
    int n = blockIdx.x * 4 + threadIdx.y;
    int c = threadIdx.x;
    const float* __restrict__ in = d_T1 + (k - 1) * T1_SLOT;
    int beg = d_row1[n], end = d_row1[n + 1];
    if (c < D1v) {
        float acc = 0.0f;
        for (int e = beg; e < end; e++)
            acc += d_cval1[e] * __ldg(&in[d_csrc1[e] * D1v + c]);
        float r;
        if (k == 1) r = acc;
        else        r = 2.0f * acc - d_T1[(k - 2) * T1_SLOT + n * D1v + c];
        d_T1[k * T1_SLOT + n * D1v + c] = r;
    }
}

__global__ void prop2_kernel(int k) {
    int n = blockIdx.x;
    int c = threadIdx.x;
    int b = c >> 6, d = c & 63;
    const float* __restrict__ in = d_T2g + (k - 1) * T2_SLOT + b * T2_BOFF;
    int beg = d_row2[n], end = d_row2[n + 1];
    float acc = 0.0f;
    for (int e = beg; e < end; e++)
        acc += d_cval2[e] * __ldg(&in[d_csrc2[e] * 64 + d]);
    float r;
    if (k == 1) r = acc;
    else        r = 2.0f * acc - d_T2g[(k - 2) * T2_SLOT + b * T2_BOFF + n * 64 + d];
    d_T2g[k * T2_SLOT + b * T2_BOFF + n * 64 + d] = r;
}

// ---------------- einsum 1 (256-thread blocks) ----------------
__global__ void einsum1_kernel(const float* __restrict__ W1, const float* __restrict__ b1) {
    __shared__ __align__(16) float sW[Kv * Tv * G1v];
    for (int i = threadIdx.x; i < Kv * Tv * G1v; i += 256) sW[i] = W1[i];
    __syncthreads();
    int t = blockIdx.x * 256 + threadIdx.x;
    int n = t >> 2, b = t & 3;
    float4 acc[16];
#pragma unroll
    for (int q = 0; q < 16; q++) acc[q] = make_float4(0.f, 0.f, 0.f, 0.f);
    for (int k = 0; k < Kv; k++) {
        const float* tp = d_T1 + k * T1_SLOT + n * D1v + b;
        const float* wp = sW + k * (Tv * G1v);
        for (int d = 0; d < Tv; d++) {
            float tv = __ldg(&tp[d * 4]);
            const float4* w4 = (const float4*)(wp + d * G1v);
#pragma unroll
            for (int q = 0; q < 16; q++) {
                float4 w = w4[q];
                acc[q].x += tv * w.x; acc[q].y += tv * w.y;
                acc[q].z += tv * w.z; acc[q].w += tv * w.w;
            }
        }
    }
    float* yp = d_y1 + n * 256 + b;
#pragma unroll
    for (int q = 0; q < 16; q++) {
        int g0 = q * 4;
        yp[(g0 + 0) * 4] = fmaxf(acc[q].x + b1[g0 + 0], 0.0f);
        yp[(g0 + 1) * 4] = fmaxf(acc[q].y + b1[g0 + 1], 0.0f);
        yp[(g0 + 2) * 4] = fmaxf(acc[q].z + b1[g0 + 2], 0.0f);
        yp[(g0 + 3) * 4] = fmaxf(acc[q].w + b1[g0 + 3], 0.0f);
    }
}

// ---------------- y1 -> transposed bf16 hi/lo split ----------------
__global__ void y1split_kernel() {
    __shared__ float tile[32][33];
    int k0 = blockIdx.x * 32, c0 = blockIdx.y * 32;
    int tx = threadIdx.x, ty = threadIdx.y;   // 32 x 8
#pragma unroll
    for (int i = 0; i < 4; i++)
        tile[ty + 8 * i][tx] = d_y1[(k0 + ty + 8 * i) * 256 + c0 + tx];
    __syncthreads();
#pragma unroll
    for (int i = 0; i < 4; i++) {
        int c = c0 + ty + 8 * i;
        float v = tile[tx][ty + 8 * i];
        __nv_bfloat16 h = __float2bfloat16(v);
        float lo = v - __bfloat162float(h);
        long long idx = (long long)c * N1v + k0 + tx;
        d_y1t_hi[idx] = __bfloat16_as_ushort(h);
        d_y1t_lo[idx] = __bfloat16_as_ushort(__float2bfloat16(lo));
    }
}

// ---------------- warp-MMA pooling GEMM (cp.async 3-stage pipeline) ----------------
// C[4096,256] = b_map @ y1, bf16 3-term split (hi*hi + lo*hi + hi*lo), fp32 acc.
// CTA tile 128x128, KB=64, grid (KSPLIT=2, 32, 2). Data pre-split in gmem.
#define KSPLIT 2
#define KB2 64
#define ASTRIDE 72                    // bf16 units per smem row (64 + 8 pad)
#define MAT_BYTES (128 * ASTRIDE * 2) // 18432
#define STG_BYTES (4 * MAT_BYTES)     // 73728
#define NSTAGE 3
#define SMEM_GEMM_TOTAL (NSTAGE * STG_BYTES)   // 221184

__device__ __forceinline__ void fill_async(uint32_t sbase, int s, int m0, int n0, int kblk) {
    int t = threadIdx.x;
    uint32_t ah = sbase + s * STG_BYTES;
    uint32_t al = ah + MAT_BYTES;
    uint32_t bh = al + MAT_BYTES;
    uint32_t bl = bh + MAT_BYTES;
#pragma unroll
    for (int i = 0; i < 4; i++) {
        int idx = t + 256 * i;            // 0..1023: (row, 16B-chunk)
        int r = idx >> 3, c = (idx & 7) * 8;
        uint32_t so = (uint32_t)(r * ASTRIDE + c) * 2;
        long long ka = ((long long)(m0 + r) * N1v + kblk + c) * 2;
        cp16(ah + so, (const char*)d_A_hi + ka);
        cp16(al + so, (const char*)d_A_lo + ka);
        long long kb = ((long long)(n0 + r) * N1v + kblk + c) * 2;
        cp16(bh + so, (const char*)d_y1t_hi + kb);
        cp16(bl + so, (const char*)d_y1t_lo + kb);
    }
}

__global__ void __launch_bounds__(256, 1) pool_gemm_mma(const float* __restrict__ Aunused) {
    extern __shared__ __align__(16) char smem[];
    uint32_t sbase = smem_to_u32(smem);
    int tid = threadIdx.x, wid = tid >> 5, lid = tid & 31;
    int m0 = blockIdx.y * 128, n0 = blockIdx.z * 128;
    int kbase = blockIdx.x * (N1v / KSPLIT);
    const int NB = (N1v / KSPLIT) / KB2;      // 64
    int wm = (wid >> 1) * 32;
    int wn = (wid & 1) * 64;

    float acc[2][8][4];
#pragma unroll
    for (int mt = 0; mt < 2; mt++)
#pragma unroll
        for (int nt = 0; nt < 8; nt++)
#pragma unroll
            for (int q = 0; q < 4; q++) acc[mt][nt][q] = 0.0f;

    int arow = wm + (lid & 15);
    int acol = (lid >> 4) * 8;
    int l16 = lid & 15;
    int brow = wn + (l16 & 7);
    int bcol = ((l16 >> 3) & 1) * 8;

    fill_async(sbase, 0, m0, n0, kbase);            CP_COMMIT();
    fill_async(sbase, 1, m0, n0, kbase + KB2);      CP_COMMIT();
    fill_async(sbase, 2, m0, n0, kbase + 2 * KB2);  CP_COMMIT();

    for (int it = 0; it < NB; it++) {
        CP_WAIT2();
        __syncthreads();
        int s = it % NSTAGE;
        uint32_t aHiB = sbase + s * STG_BYTES;
        uint32_t aLoB = aHiB + MAT_BYTES;
        uint32_t bHiB = aLoB + MAT_BYTES;
        uint32_t bLoB = bHiB + MAT_BYTES;
#pragma unroll
        for (int k16 = 0; k16 < KB2 / 16; k16++) {
            uint32_t ah[2][4], alo[2][4], bhf[8][2], blf[8][2];
#pragma unroll
            for (int mt = 0; mt < 2; mt++) {
                uint32_t off = (uint32_t)(((arow + mt * 16) * ASTRIDE + k16 * 16 + acol) * 2);
                ldsm_x4(ah[mt],  aHiB + off);
                ldsm_x4(alo[mt], aLoB + off);
            }
#pragma unroll
            for (int nt = 0; nt < 8; nt++) {
                uint32_t off = (uint32_t)(((brow + nt * 8) * ASTRIDE + k16 * 16 + bcol) * 2);
                ldsm_x2(bhf[nt], bHiB + off);
                ldsm_x2(blf[nt], bLoB + off);
            }
#pragma unroll
            for (int mt = 0; mt < 2; mt++)
#pragma unroll
                for (int nt = 0; nt < 8; nt++) {
                    mma_bf16(acc[mt][nt], ah[mt],  bhf[nt]);
                    mma_bf16(acc[mt][nt], alo[mt], bhf[nt]);
                    mma_bf16(acc[mt][nt], ah[mt],  blf[nt]);
                }
        }
        __syncthreads();
        if (it + NSTAGE < NB)
            fill_async(sbase, s, m0, n0, kbase + (it + NSTAGE) * KB2);
        CP_COMMIT();
    }

    // epilogue: atomic-accumulate into d_T2g slot 0 ([b][m][g], col = g*4+b)
#pragma unroll
    for (int mt = 0; mt < 2; mt++) {
        int m_lo = m0 + wm + mt * 16 + (lid >> 2);
        int m_hi = m_lo + 8;
#pragma unroll
        for (int nt = 0; nt < 8; nt++) {
            int c0 = n0 + wn + nt * 8 + (lid & 3) * 2;
            int c1 = c0 + 1;
            atomicAdd(&d_T2g[(c0 & 3) * T2_BOFF + m_lo * 64 + (c0 >> 2)], acc[mt][nt][0]);
            atomicAdd(&d_T2g[(c1 & 3) * T2_BOFF + m_lo * 64 + (c1 >> 2)], acc[mt][nt][1]);
            atomicAdd(&d_T2g[(c0 & 3) * T2_BOFF + m_hi * 64 + (c0 >> 2)], acc[mt][nt][2]);
            atomicAdd(&d_T2g[(c1 & 3) * T2_BOFF + m_hi * 64 + (c1 >> 2)], acc[mt][nt][3]);
        }
    }
}

// ---------------- einsum 2 (128-thread blocks) ----------------
__global__ void einsum2_kernel(const float* __restrict__ W2, const float* __restrict__ b2) {
    __shared__ __align__(16) float sW[64 * 32];
    int t = blockIdx.x * 128 + threadIdx.x;
    int n = t >> 2, b = t & 3;
    float4 acc[8];
#pragma unroll
    for (int q = 0; q < 8; q++) acc[q] = make_float4(0.f, 0.f, 0.f, 0.f);
    for (int k = 0; k < Kv; k++) {
        __syncthreads();
        for (int i = threadIdx.x; i < 2048; i += 128) sW[i] = W2[k * 2048 + i];
        __syncthreads();
        const float* tp = d_T2g + k * T2_SLOT + b * T2_BOFF + n * 64;
        for (int d = 0; d < 64; d++) {
            float tv = __ldg(&tp[d]);
            const float4* w4 = (const float4*)(sW + d * 32);
#pragma unroll
            for (int q = 0; q < 8; q++) {
                float4 w = w4[q];
                acc[q].x += tv * w.x; acc[q].y += tv * w.y;
                acc[q].z += tv * w.z; acc[q].w += tv * w.w;
            }
        }
    }
    float* yp = d_y2 + n * 128 + b;
#pragma unroll
    for (int q = 0; q < 8; q++) {
        int g0 = q * 4;
        yp[(g0 + 0) * 4] = acc[q].x + b2[g0 + 0];
        yp[(g0 + 1) * 4] = acc[q].y + b2[g0 + 1];
        yp[(g0 + 2) * 4] = acc[q].z + b2[g0 + 2];
        yp[(g0 + 3) * 4] = acc[q].w + b2[g0 + 3];
    }
}

// ---------------- FC (split-K) + log_softmax ----------------
__global__ void fc_kernel(const float* __restrict__ fcw) {
    int bc = blockIdx.x;                 // 0..23 = b*6 + c
    int b = bc / 6, c = bc - b * 6;
    int ks = blockIdx.y;                 // 0..7
    const float4* w4 = (const float4*)(fcw + (long long)c * 131072);
    const float4* h4 = (const float4*)(d_y2 + b * 131072);
    float s = 0.0f;
    int beg = ks * 4096, end = beg + 4096;
    for (int i = beg + threadIdx.x; i < end; i += 256) {
        float4 a = __ldg(&w4[i]);
        float4 h = h4[i];
        s += a.x * h.x + a.y * h.y + a.z * h.z + a.w * h.w;
    }
    __shared__ float sh[256];
    sh[threadIdx.x] = s;
    __syncthreads();
    for (int off = 128; off > 0; off >>= 1) {
        if (threadIdx.x < off) sh[threadIdx.x] += sh[threadIdx.x + off];
        __syncthreads();
    }
    if (threadIdx.x == 0) atomicAdd(&d_logits[bc], sh[0]);
}

__global__ void lsm_kernel(float* __restrict__ out, const float* __restrict__ fcb) {
    int b = threadIdx.x;
    if (b < Bv) {
        float l[Cv];
        float m = -1e30f;
#pragma unroll
        for (int c = 0; c < Cv; c++) { l[c] = d_logits[b * Cv + c] + fcb[c]; m = fmaxf(m, l[c]); }
        float s = 0.0f;
#pragma unroll
        for (int c = 0; c < Cv; c++) s += expf(l[c] - m);
        float L = logf(s);
#pragma unroll
        for (int c = 0; c < Cv; c++) out[b * Cv + c] = l[c] - m - L;
    }
}

// ---------------- launch ----------------
extern "C" void kernel_launch(void* const* d_in, const int* in_sizes, int n_in,
                              void* d_out, int out_size) {
    const float* x    = (const float*)d_in[0];
    const void*  ei1  = d_in[1];
    const float* ew1  = (const float*)d_in[2];
    const void*  ei2  = d_in[3];
    const float* ew2  = (const float*)d_in[4];
    const float* bmap = (const float*)d_in[5];
    const float* W1   = (const float*)d_in[6];
    const float* b1   = (const float*)d_in[7];
    const float* W2   = (const float*)d_in[8];
    const float* b2   = (const float*)d_in[9];
    const float* fcw  = (const float*)d_in[10];
    const float* fcb  = (const float*)d_in[11];
    float* out = (float*)d_out;

    cudaFuncSetAttribute(pool_gemm_mma, cudaFuncAttributeMaxDynamicSharedMemorySize,
                         SMEM_GEMM_TOTAL);

    detect_kernel<<<1, 32>>>((const int*)ei1);
    zero_kernel<<<T2_SLOT / 256, 256>>>();
    aconv_kernel<<<(N2v / 1) * (N1v / 1024), 256>>>(bmap);   // 32768 blocks x 1024 fp32
    deg1_kernel<<<E1v / 256, 256>>>(ei1, ew1);
    deg2_kernel<<<E2v / 256, 256>>>(ei2, ew2);
    dinv_kernel<<<N1v / 256, 256>>>();
    scan_kernel<<<1, 1024>>>();
    fill1_kernel<<<E1v / 256, 256>>>(ei1, ew1);
    fill2_kernel<<<E2v / 256, 256>>>(ei2, ew2);
    transpose_kernel<<<T1_SLOT / 256, 256>>>(x);

    for (int k = 1; k < Kv; k++)
        prop1_kernel<<<N1v / 4, dim3(64, 4)>>>(k);
    einsum1_kernel<<<(N1v * Bv) / 256, 256>>>(W1, b1);

    y1split_kernel<<<dim3(N1v / 32, 256 / 32), dim3(32, 8)>>>();
    pool_gemm_mma<<<dim3(KSPLIT, 32, 2), 256, SMEM_GEMM_TOTAL>>>(bmap);

    for (int k = 1; k < Kv; k++)
        prop2_kernel<<<N2v, 256>>>(k);
    einsum2_kernel<<<(N2v * Bv) / 128, 128>>>(W2, b2);

    fc_kernel<<<dim3(Bv * Cv, 8), 256>>>(fcw);
    lsm_kernel<<<1, 32>>>(out, fcb);
}